// round 15
// baseline (speedup 1.0000x reference)
#include <cuda_runtime.h>
#include <cuda_fp16.h>

// Problem constants (match reference)
#define NGRID 512
#define NB    10      // bond types
#define NM    16      // integrals
#define E_EDGES 2000000
#define N_NODES 500000

// Derived output offsets (floats)
#define OUT_OVL_OFF  (E_EDGES * NM)          // 32,000,000
#define OUT_NODE_OFF (2 * E_EDGES * NM)      // 64,000,000

// Grid-pair-interleaved fp16 table.
// Entry (b, i0) = 128 B = one cache line = 32 words; word p (4 B) holds the
// half pair ( v_p[i0] , v_p[i0+1] ) where v_p = hop m=p (p<16) else ovl m=p-16.
// One LDG.128 per 8-lane group member fetches 4 m-values with BOTH grid rows.
// Size: 10 * 512 * 128 B = 640 KB.
__device__ __align__(128) __half g_tab[NB * NGRID * 64];

#define NWORDS  (NB * NGRID * 32)     // 163,840 table words (4 B each)
#define EPT     8                     // edges per thread
#define ETHREADS (E_EDGES)            // 2,000,000 edge threads (8 lanes x E/8)

// 1/DX as compile-time fp32 constant (DX = 9/511)
#define INV_DX  ((float)((double)(NGRID - 1) / (10.0 - 1.0)))

// ---------------------------------------------------------------------------
// Kernel 1: pair-interleaved table build, one thread per 4B WORD (coalesced).
// ---------------------------------------------------------------------------
__global__ void __launch_bounds__(256)
prep_kernel(const float* __restrict__ hop,
            const float* __restrict__ ovl) {
    int idx = blockIdx.x * blockDim.x + threadIdx.x;
    if (idx >= NWORDS) return;
    int p = idx & 31;
    int g = (idx >> 5) & (NGRID - 1);
    int b = idx >> 14;                          // idx / (512*32)
    int m = p & (NM - 1);
    const float* src = (p < NM) ? hop : ovl;
    int srow = (b * NM + m) << 9;               // (b*16+m)*512
    int g1 = min(g + 1, NGRID - 1);
    float lo = __ldg(src + srow + g);
    float hi = __ldg(src + srow + g1);
    __half2 w = __floats2half2_rn(lo, hi);
    ((__half2*)g_tab)[idx] = w;                 // coalesced: p fastest
}

// ---------------------------------------------------------------------------
// Kernel 2: edges (8 lanes/edge, EPT=8 edges/thread, LOCAL k-remap) + nodes.
// Thread t: gp = t>>3, slot s = t&7.
// Edge for unroll step k:  e = (gp>>2)*32 + k*4 + (gp&3)
//   -> warp owns 32 consecutive edges (scalar loads: 1 line; stores: one
//      contiguous 2KB run per array). Gather: ONE LDG.128 at entry(b,i0),
//      words [4s,4s+4); line fully consumed by the 8-lane group.
// Output stores use __stwt (write-through): outputs are never re-read, so
// skip L2 allocation entirely and free LTS bandwidth for the table gathers.
// ---------------------------------------------------------------------------
__global__ void __launch_bounds__(256)
main_kernel(const float* __restrict__ rij,
            const int*   __restrict__ edge_type,
            const int*   __restrict__ atom_type,
            const float* __restrict__ onsiteE,
            float*       __restrict__ out) {
    int t = blockIdx.x * blockDim.x + threadIdx.x;

    if (t < ETHREADS) {
        int gp = t >> 3;
        int s  = t & 7;
        int ebase = ((gp >> 2) << 5) + (gp & 3);   // + k*4 per unroll step
        const uint4* tab4 = (const uint4*)g_tab;   // 8 uint4 per 128B entry

        float rv[EPT];
        int   bt[EPT];
        #pragma unroll
        for (int k = 0; k < EPT; k++) {
            rv[k] = __ldg(rij + ebase + (k << 2));
            bt[k] = __ldg(edge_type + ebase + (k << 2));
        }

        float frac[EPT];
        int row[EPT];
        #pragma unroll
        for (int k = 0; k < EPT; k++) {
            float tt = (rv[k] - 1.0f) * INV_DX;    // tt >= 0 by input domain
            int i0 = min((int)tt, NGRID - 2);
            frac[k] = tt - (float)i0;
            row[k] = (((bt[k] << 9) + i0) << 3) + s;   // uint4 index
        }

        uint4 d[EPT];
        #pragma unroll
        for (int k = 0; k < EPT; k++)
            d[k] = __ldg(tab4 + row[k]);

        int is_ovl = s >> 2;
        int q = s & 3;
        float4* outv = (float4*)out;
        #pragma unroll
        for (int k = 0; k < EPT; k++) {
            float2 p0 = __half22float2(*reinterpret_cast<const __half2*>(&d[k].x));
            float2 p1 = __half22float2(*reinterpret_cast<const __half2*>(&d[k].y));
            float2 p2 = __half22float2(*reinterpret_cast<const __half2*>(&d[k].z));
            float2 p3 = __half22float2(*reinterpret_cast<const __half2*>(&d[k].w));
            float4 res;
            res.x = fmaf(p0.y - p0.x, frac[k], p0.x);
            res.y = fmaf(p1.y - p1.x, frac[k], p1.x);
            res.z = fmaf(p2.y - p2.x, frac[k], p2.x);
            res.w = fmaf(p3.y - p3.x, frac[k], p3.x);
            int e = ebase + (k << 2);
            int dst4 = is_ovl * (OUT_OVL_OFF >> 2) + (e << 2) + q;
            __stwt(outv + dst4, res);
        }
    } else {
        int n = t - ETHREADS;
        if (n < N_NODES) {
            int at = __ldg(atom_type + n);
            float4 v = __ldg((const float4*)onsiteE + at);
            __stwt(((float4*)(out + OUT_NODE_OFF)) + n, v);
        }
    }
}

// ---------------------------------------------------------------------------
// Launch
// ---------------------------------------------------------------------------
extern "C" void kernel_launch(void* const* d_in, const int* in_sizes, int n_in,
                              void* d_out, int out_size) {
    const float* rij       = (const float*)d_in[0];
    const int*   edge_type = (const int*)d_in[1];
    const int*   atom_type = (const int*)d_in[2];
    const float* hop       = (const float*)d_in[3];
    const float* ovl       = (const float*)d_in[4];
    const float* onsiteE   = (const float*)d_in[5];
    float* out = (float*)d_out;

    // 1) pair-interleaved table build (coalesced writes)
    {
        int blk = 256;
        prep_kernel<<<(NWORDS + blk - 1) / blk, blk>>>(hop, ovl);
    }
    // 2) edges + nodes
    {
        int total = ETHREADS + N_NODES;             // 2,500,000
        int blk = 256;
        main_kernel<<<(total + blk - 1) / blk, blk>>>(rij, edge_type,
                                                      atom_type, onsiteE, out);
    }
}

// round 16
// speedup vs baseline: 1.1362x; 1.1362x over previous
#include <cuda_runtime.h>
#include <cuda_fp16.h>

// Problem constants (match reference)
#define NGRID 512
#define NB    10      // bond types
#define NM    16      // integrals
#define E_EDGES 2000000
#define N_NODES 500000

// Derived output offsets (floats)
#define OUT_OVL_OFF  (E_EDGES * NM)          // 32,000,000
#define OUT_NODE_OFF (2 * E_EDGES * NM)      // 64,000,000

// Grid-pair-interleaved fp16 table.
// Entry (b, i0) = 128 B = one cache line = 32 words; word p (4 B) holds the
// half pair ( v_p[i0] , v_p[i0+1] ) where v_p = hop m=p (p<16) else ovl m=p-16.
// One LDG.128 per 8-lane group member fetches 4 m-values with BOTH grid rows.
// Size: 10 * 512 * 128 B = 640 KB.
__device__ __align__(128) __half g_tab[NB * NGRID * 64];

#define NWORDS  (NB * NGRID * 32)     // 163,840 table words (4 B each)
#define EPT     8                     // edges per thread
#define ETHREADS (E_EDGES)            // 2,000,000 edge threads (8 lanes x E/8)

// 1/DX as compile-time fp32 constant (DX = 9/511)
#define INV_DX  ((float)((double)(NGRID - 1) / (10.0 - 1.0)))

// ---------------------------------------------------------------------------
// Kernel 1: pair-interleaved table build, one thread per 4B WORD (coalesced).
// idx -> p (word-in-entry, fastest), g, b  => warp writes 128B contiguous.
// p < 16: hop integral m=p; p >= 16: ovl integral m=p-16.
// word = ( v[g] , v[min(g+1,511)] ) as half2. Entry g=511 is never read.
// ---------------------------------------------------------------------------
__global__ void __launch_bounds__(256)
prep_kernel(const float* __restrict__ hop,
            const float* __restrict__ ovl) {
    int idx = blockIdx.x * blockDim.x + threadIdx.x;
    if (idx >= NWORDS) return;
    int p = idx & 31;
    int g = (idx >> 5) & (NGRID - 1);
    int b = idx >> 14;                          // idx / (512*32)
    int m = p & (NM - 1);
    const float* src = (p < NM) ? hop : ovl;
    int srow = (b * NM + m) << 9;               // (b*16+m)*512
    int g1 = min(g + 1, NGRID - 1);
    float lo = __ldg(src + srow + g);
    float hi = __ldg(src + srow + g1);
    __half2 w = __floats2half2_rn(lo, hi);
    ((__half2*)g_tab)[idx] = w;                 // coalesced: p fastest
}

// ---------------------------------------------------------------------------
// Kernel 2: edges (8 lanes/edge, EPT=8 edges/thread, LOCAL k-remap) + nodes.
// Thread t: gp = t>>3, slot s = t&7.
// Edge for unroll step k:  e = (gp>>2)*32 + k*4 + (gp&3)
//   -> a warp (4 consecutive gp) owns 32 CONSECUTIVE edges:
//      * all 8 rij (and edge_type) loads of the warp hit ONE 128B line
//      * per-k stores cover 4 consecutive edges = 256B contiguous per array
//      * warp's total store footprint = one contiguous 2KB run per array
// Gather: ONE LDG.128 at entry(b,i0), words [4s,4s+4); line fully consumed
// by the 8-lane group. res = lo + (hi-lo)*frac (fp32).
// Stores: __stcs (evict-first, L2-allocating) — measured best policy
// (evict_last on loads: neutral; __stwt on stores: -6us regression).
// ---------------------------------------------------------------------------
__global__ void __launch_bounds__(256)
main_kernel(const float* __restrict__ rij,
            const int*   __restrict__ edge_type,
            const int*   __restrict__ atom_type,
            const float* __restrict__ onsiteE,
            float*       __restrict__ out) {
    int t = blockIdx.x * blockDim.x + threadIdx.x;

    if (t < ETHREADS) {
        int gp = t >> 3;
        int s  = t & 7;
        int ebase = ((gp >> 2) << 5) + (gp & 3);   // + k*4 per unroll step
        const uint4* tab4 = (const uint4*)g_tab;   // 8 uint4 per 128B entry

        float rv[EPT];
        int   bt[EPT];
        #pragma unroll
        for (int k = 0; k < EPT; k++) {
            rv[k] = __ldg(rij + ebase + (k << 2));
            bt[k] = __ldg(edge_type + ebase + (k << 2));
        }

        float frac[EPT];
        int row[EPT];
        #pragma unroll
        for (int k = 0; k < EPT; k++) {
            float tt = (rv[k] - 1.0f) * INV_DX;    // tt >= 0 by input domain
            int i0 = min((int)tt, NGRID - 2);
            frac[k] = tt - (float)i0;
            row[k] = (((bt[k] << 9) + i0) << 3) + s;   // uint4 index
        }

        uint4 d[EPT];
        #pragma unroll
        for (int k = 0; k < EPT; k++)
            d[k] = __ldg(tab4 + row[k]);

        int is_ovl = s >> 2;
        int q = s & 3;
        float4* outv = (float4*)out;
        #pragma unroll
        for (int k = 0; k < EPT; k++) {
            float2 p0 = __half22float2(*reinterpret_cast<const __half2*>(&d[k].x));
            float2 p1 = __half22float2(*reinterpret_cast<const __half2*>(&d[k].y));
            float2 p2 = __half22float2(*reinterpret_cast<const __half2*>(&d[k].z));
            float2 p3 = __half22float2(*reinterpret_cast<const __half2*>(&d[k].w));
            float4 res;
            res.x = fmaf(p0.y - p0.x, frac[k], p0.x);
            res.y = fmaf(p1.y - p1.x, frac[k], p1.x);
            res.z = fmaf(p2.y - p2.x, frac[k], p2.x);
            res.w = fmaf(p3.y - p3.x, frac[k], p3.x);
            int e = ebase + (k << 2);
            int dst4 = is_ovl * (OUT_OVL_OFF >> 2) + (e << 2) + q;
            __stcs(outv + dst4, res);
        }
    } else {
        int n = t - ETHREADS;
        if (n < N_NODES) {
            int at = __ldg(atom_type + n);
            float4 v = __ldg((const float4*)onsiteE + at);
            __stcs(((float4*)(out + OUT_NODE_OFF)) + n, v);
        }
    }
}

// ---------------------------------------------------------------------------
// Launch
// ---------------------------------------------------------------------------
extern "C" void kernel_launch(void* const* d_in, const int* in_sizes, int n_in,
                              void* d_out, int out_size) {
    const float* rij       = (const float*)d_in[0];
    const int*   edge_type = (const int*)d_in[1];
    const int*   atom_type = (const int*)d_in[2];
    const float* hop       = (const float*)d_in[3];
    const float* ovl       = (const float*)d_in[4];
    const float* onsiteE   = (const float*)d_in[5];
    float* out = (float*)d_out;

    // 1) pair-interleaved table build (coalesced writes)
    {
        int blk = 256;
        prep_kernel<<<(NWORDS + blk - 1) / blk, blk>>>(hop, ovl);
    }
    // 2) edges + nodes
    {
        int total = ETHREADS + N_NODES;             // 2,500,000
        int blk = 256;
        main_kernel<<<(total + blk - 1) / blk, blk>>>(rij, edge_type,
                                                      atom_type, onsiteE, out);
    }
}